// round 16
// baseline (speedup 1.0000x reference)
#include <cuda_runtime.h>
#include <math.h>
#include <stdint.h>

#define SEQ 2048
#define DM  2048
#define NH  16
#define DK  128
#define FIB 64

// ---------------- static scratch ----------------
__device__ float g_X [(size_t)SEQ * DM];
__device__ float g_WQ[(size_t)DM * DM];
__device__ float g_WK[(size_t)DM * DM];
__device__ float g_WV[(size_t)DM * DM];
__device__ float g_WO[(size_t)DM * DM];
__device__ float g_FW[(size_t)FIB * DM];
__device__ float g_Q [(size_t)SEQ * DM];   // pre-scaled by 1/sqrt(dk), tf32-rounded
__device__ float g_K [(size_t)SEQ * DM];
__device__ float g_VT[(size_t)DM * SEQ];   // V transposed (DM x SEQ)
__device__ float g_O [(size_t)SEQ * DM];
__device__ float g_FP[(size_t)SEQ * FIB];
__device__ float g_G [(size_t)SEQ * FIB];
__device__ float g_MOD[(size_t)SEQ * SEQ]; // pre-scaled by 0.1
__device__ float g_xbar[DM];
__device__ float g_mi[FIB];
__device__ float g_metric[FIB * FIB];
__device__ float g_curv[SEQ];              // pre-scaled by 0.1

// ---------------- helpers ----------------
__device__ __forceinline__ uint32_t smem_u32(const void* p) {
    uint32_t a;
    asm("{ .reg .u64 t; cvta.to.shared.u64 t, %1; cvt.u32.u64 %0, t; }" : "=r"(a) : "l"(p));
    return a;
}
__device__ __forceinline__ float tf32r(float x) {
    uint32_t u;
    asm("cvt.rna.tf32.f32 %0, %1;" : "=r"(u) : "f"(x));
    return __uint_as_float(u);
}
__device__ __forceinline__ void cp16(uint32_t s, const void* g) {
    asm volatile("cp.async.cg.shared.global [%0], [%1], 16;" :: "r"(s), "l"(g));
}
__device__ __forceinline__ void cp_commit() { asm volatile("cp.async.commit_group;" ::: "memory"); }
__device__ __forceinline__ void cp_wait_all() { asm volatile("cp.async.wait_group 0;" ::: "memory"); }

// m16n8k8 tf32 mma: D = A*B + D (A row-major, B col-major)
__device__ __forceinline__ void mma8(float* c, const uint32_t* a, const uint32_t* b) {
    asm volatile(
        "mma.sync.aligned.m16n8k8.row.col.f32.tf32.tf32.f32 "
        "{%0,%1,%2,%3}, {%4,%5,%6,%7}, {%8,%9}, {%0,%1,%2,%3};"
        : "+f"(c[0]), "+f"(c[1]), "+f"(c[2]), "+f"(c[3])
        : "r"(a[0]), "r"(a[1]), "r"(a[2]), "r"(a[3]), "r"(b[0]), "r"(b[1]));
}

#define KT    32
#define ASTR  36
#define TILEF (128 * ASTR)
#define CHUNKF (128 * ASTR)     // one 128x32 chunk in floats (4608)

// ---------------- tf32 tensor-core GEMM: C = alpha*A(MxK)·B(NxK)^T + epi ----
__global__ __launch_bounds__(256) void mma_gemm(
    const float* __restrict__ A, const float* __restrict__ B, float* __restrict__ C,
    int N, int K, int lda, int ldb, int ldc,
    long long zA, long long zB, long long zC,
    float alpha, const float* __restrict__ bias,
    int storeT, int roundC)
{
    extern __shared__ float smf[];
    float* A0 = smf;
    float* B0 = A0 + TILEF;
    float* A1 = B0 + TILEF;
    float* B1 = A1 + TILEF;

    const int tid = threadIdx.x;
    const int wid = tid >> 5, lane = tid & 31;
    const int wm = wid >> 2, wn = wid & 3;
    const int g = lane >> 2, t = lane & 3;

    A += (long long)blockIdx.z * zA;
    B += (long long)blockIdx.z * zB;
    C += (long long)blockIdx.z * zC;
    const int bm = blockIdx.y * 128;
    const int bn = blockIdx.x * 128;
    const float* Ab = A + (long long)bm * lda;
    const float* Bb = B + (long long)bn * ldb;

    float acc[4][4][4];
#pragma unroll
    for (int mt = 0; mt < 4; mt++)
#pragma unroll
        for (int nt = 0; nt < 4; nt++)
#pragma unroll
            for (int r = 0; r < 4; r++) acc[mt][nt][r] = 0.f;

    const int NKT = K / KT;

    auto load_tiles = [&](float* As, float* Bs, int k0) {
        for (int c = tid; c < 1024; c += 256) {
            const int row = c >> 3;
            const int k4  = (c & 7) << 2;
            cp16(smem_u32(As + row * ASTR + k4), Ab + (long long)row * lda + k0 + k4);
            if (bn + row < N) {
                cp16(smem_u32(Bs + row * ASTR + k4), Bb + (long long)row * ldb + k0 + k4);
            } else {
                *(float4*)(Bs + row * ASTR + k4) = make_float4(0.f, 0.f, 0.f, 0.f);
            }
        }
    };

    load_tiles(A0, B0, 0);
    cp_commit();

    for (int kt = 0; kt < NKT; kt++) {
        float* As = (kt & 1) ? A1 : A0;
        float* Bs = (kt & 1) ? B1 : B0;
        cp_wait_all();
        __syncthreads();
        if (kt + 1 < NKT) {
            load_tiles((kt & 1) ? A0 : A1, (kt & 1) ? B0 : B1, (kt + 1) * KT);
            cp_commit();
        }
#pragma unroll
        for (int ks = 0; ks < 4; ks++) {
            const int k = ks * 8;
            uint32_t af[4][4], bf[4][2];
#pragma unroll
            for (int mt = 0; mt < 4; mt++) {
                const int r = wm * 64 + mt * 16 + g;
                af[mt][0] = __float_as_uint(As[r * ASTR + k + t]);
                af[mt][1] = __float_as_uint(As[(r + 8) * ASTR + k + t]);
                af[mt][2] = __float_as_uint(As[r * ASTR + k + t + 4]);
                af[mt][3] = __float_as_uint(As[(r + 8) * ASTR + k + t + 4]);
            }
#pragma unroll
            for (int nt = 0; nt < 4; nt++) {
                const int cidx = wn * 32 + nt * 8 + g;
                bf[nt][0] = __float_as_uint(Bs[cidx * ASTR + k + t]);
                bf[nt][1] = __float_as_uint(Bs[cidx * ASTR + k + t + 4]);
            }
#pragma unroll
            for (int mt = 0; mt < 4; mt++)
#pragma unroll
                for (int nt = 0; nt < 4; nt++)
                    mma8(acc[mt][nt], af[mt], bf[nt]);
        }
        __syncthreads();
    }

    if (!storeT) {
#pragma unroll
        for (int mt = 0; mt < 4; mt++) {
#pragma unroll
            for (int nt = 0; nt < 4; nt++) {
                const int row0 = bm + wm * 64 + mt * 16 + g;
                const int col0 = bn + wn * 32 + nt * 8 + 2 * t;
                if (col0 < N) {
#pragma unroll
                    for (int h = 0; h < 2; h++) {
                        const int row = row0 + h * 8;
                        float v0 = acc[mt][nt][h * 2 + 0] * alpha;
                        float v1 = acc[mt][nt][h * 2 + 1] * alpha;
                        if (bias) { v0 += bias[col0]; v1 += bias[col0 + 1]; }
                        if (roundC) { v0 = tf32r(v0); v1 = tf32r(v1); }
                        *(float2*)(C + (long long)row * ldc + col0) = make_float2(v0, v1);
                    }
                }
            }
        }
    } else {
        __syncthreads();
        for (int p = 0; p < 4; p++) {
            if (wn == p) {
#pragma unroll
                for (int mt = 0; mt < 4; mt++) {
#pragma unroll
                    for (int nt = 0; nt < 4; nt++) {
                        const int r0 = wm * 64 + mt * 16 + g;
                        const int cl = nt * 8 + 2 * t;
                        smf[cl * 132 + r0]           = acc[mt][nt][0];
                        smf[(cl + 1) * 132 + r0]     = acc[mt][nt][1];
                        smf[cl * 132 + r0 + 8]       = acc[mt][nt][2];
                        smf[(cl + 1) * 132 + r0 + 8] = acc[mt][nt][3];
                    }
                }
            }
            __syncthreads();
            for (int idx = tid; idx < 32 * 32; idx += 256) {
                const int c  = idx >> 5;
                const int r4 = (idx & 31) << 2;
                float4 v = *(float4*)&smf[c * 132 + r4];
                v.x *= alpha; v.y *= alpha; v.z *= alpha; v.w *= alpha;
                if (roundC) { v.x = tf32r(v.x); v.y = tf32r(v.y); v.z = tf32r(v.z); v.w = tf32r(v.w); }
                *(float4*)(C + (long long)(bn + p * 32 + c) * ldc + bm + r4) = v;
            }
            __syncthreads();
        }
    }
}

// ---------------- fused flash attention: S->softmax->PV, S never in DRAM ---
// grid (SEQ/128 q-tiles, NH heads), 256 thr. Q pre-scaled 1/sqrt(dk);
// MOD/curv pre-scaled by 0.1.
__global__ __launch_bounds__(256, 1) void flash_attn_kernel()
{
    extern __shared__ float smf[];
    float* Qs  = smf;                  // 4 chunks [128][36]
    float* Ps  = Qs + 4 * CHUNKF;      // 4 chunks [128][36]
    float* KB0 = Ps + 4 * CHUNKF;      // 128x36
    float* KB1 = KB0 + CHUNKF;
    float* red = KB1 + CHUNKF;         // [4][128]

    const int tid = threadIdx.x;
    const int wid = tid >> 5, lane = tid & 31;
    const int wm = wid >> 2, wn = wid & 3;
    const int g = lane >> 2, t = lane & 3;
    const int qt = blockIdx.x, h = blockIdx.y;
    const int qrow0 = qt * 128;

    // load full Q tile (4 dk-chunks)
    for (int kc = 0; kc < 4; kc++)
        for (int c = tid; c < 1024; c += 256) {
            const int row = c >> 3, k4 = (c & 7) << 2;
            cp16(smem_u32(Qs + kc * CHUNKF + row * ASTR + k4),
                 g_Q + (size_t)(qrow0 + row) * DM + h * DK + kc * 32 + k4);
        }
    cp_commit();

    float Oa[4][4][4];
    float mrun[4][2], lrun[4][2];
#pragma unroll
    for (int mt = 0; mt < 4; mt++) {
#pragma unroll
        for (int nt = 0; nt < 4; nt++) {
            Oa[mt][nt][0] = Oa[mt][nt][1] = Oa[mt][nt][2] = Oa[mt][nt][3] = 0.f;
        }
        mrun[mt][0] = mrun[mt][1] = -INFINITY;
        lrun[mt][0] = lrun[mt][1] = 0.f;
    }

    auto mma_tile = [&](float (&acc)[4][4][4], const float* As, const float* Bs) {
#pragma unroll
        for (int ks = 0; ks < 4; ks++) {
            const int k = ks * 8;
            uint32_t af[4][4], bf[4][2];
#pragma unroll
            for (int mt = 0; mt < 4; mt++) {
                const int r = wm * 64 + mt * 16 + g;
                af[mt][0] = __float_as_uint(As[r * ASTR + k + t]);
                af[mt][1] = __float_as_uint(As[(r + 8) * ASTR + k + t]);
                af[mt][2] = __float_as_uint(As[r * ASTR + k + t + 4]);
                af[mt][3] = __float_as_uint(As[(r + 8) * ASTR + k + t + 4]);
            }
#pragma unroll
            for (int nt = 0; nt < 4; nt++) {
                const int ci = wn * 32 + nt * 8 + g;
                bf[nt][0] = __float_as_uint(Bs[ci * ASTR + k + t]);
                bf[nt][1] = __float_as_uint(Bs[ci * ASTR + k + t + 4]);
            }
#pragma unroll
            for (int mt = 0; mt < 4; mt++)
#pragma unroll
                for (int nt = 0; nt < 4; nt++)
                    mma8(acc[mt][nt], af[mt], bf[nt]);
        }
    };

    auto load_kb = [&](float* dst, const float* gsrc, long long ld) {
        for (int c = tid; c < 1024; c += 256) {
            const int row = c >> 3, k4 = (c & 7) << 2;
            cp16(smem_u32(dst + row * ASTR + k4), gsrc + (long long)row * ld + k4);
        }
    };

    cp_wait_all();
    __syncthreads();   // Q resident

    for (int st = 0; st < 16; st++) {
        const int s0 = st * 128;
        float Sa[4][4][4];
#pragma unroll
        for (int mt = 0; mt < 4; mt++)
#pragma unroll
            for (int nt = 0; nt < 4; nt++)
                Sa[mt][nt][0] = Sa[mt][nt][1] = Sa[mt][nt][2] = Sa[mt][nt][3] = 0.f;

        // ---- S = Q' @ K^T (4 dk-chunks, double-buffered) ----
        load_kb(KB0, g_K + (size_t)s0 * DM + h * DK, DM);
        cp_commit();
        for (int kc = 0; kc < 4; kc++) {
            float* cur = (kc & 1) ? KB1 : KB0;
            float* nxt = (kc & 1) ? KB0 : KB1;
            cp_wait_all();
            __syncthreads();
            if (kc < 3) {
                load_kb(nxt, g_K + (size_t)s0 * DM + h * DK + (kc + 1) * 32, DM);
                cp_commit();
            }
            mma_tile(Sa, Qs + kc * CHUNKF, cur);
            __syncthreads();
        }

        // ---- epilogue: += MOD' + curv' ----
#pragma unroll
        for (int mt = 0; mt < 4; mt++)
#pragma unroll
            for (int hh = 0; hh < 2; hh++) {
                const int row = qrow0 + wm * 64 + mt * 16 + hh * 8 + g;
                const float* mr = g_MOD + (size_t)row * SEQ + s0;
#pragma unroll
                for (int nt = 0; nt < 4; nt++) {
                    const int cl = wn * 32 + nt * 8 + 2 * t;
                    float2 mv = *(const float2*)(mr + cl);
                    float2 cv = *(const float2*)(g_curv + s0 + cl);
                    Sa[mt][nt][hh * 2 + 0] += mv.x + cv.x;
                    Sa[mt][nt][hh * 2 + 1] += mv.y + cv.y;
                }
            }

        // ---- online softmax: tile row max ----
        float tm[4][2];
#pragma unroll
        for (int mt = 0; mt < 4; mt++)
#pragma unroll
            for (int hh = 0; hh < 2; hh++) {
                float m = -INFINITY;
#pragma unroll
                for (int nt = 0; nt < 4; nt++)
                    m = fmaxf(m, fmaxf(Sa[mt][nt][hh * 2], Sa[mt][nt][hh * 2 + 1]));
                m = fmaxf(m, __shfl_xor_sync(0xffffffffu, m, 1));
                m = fmaxf(m, __shfl_xor_sync(0xffffffffu, m, 2));
                tm[mt][hh] = m;
            }
        if (t == 0) {
#pragma unroll
            for (int mt = 0; mt < 4; mt++)
#pragma unroll
                for (int hh = 0; hh < 2; hh++)
                    red[wn * 128 + wm * 64 + mt * 16 + hh * 8 + g] = tm[mt][hh];
        }
        __syncthreads();
        float mnew[4][2], scal[4][2];
#pragma unroll
        for (int mt = 0; mt < 4; mt++)
#pragma unroll
            for (int hh = 0; hh < 2; hh++) {
                const int r = wm * 64 + mt * 16 + hh * 8 + g;
                float v = fmaxf(fmaxf(red[r], red[128 + r]),
                                fmaxf(red[256 + r], red[384 + r]));
                float mn = fmaxf(mrun[mt][hh], v);
                scal[mt][hh] = __expf(mrun[mt][hh] - mn);
                mnew[mt][hh] = mn;
                mrun[mt][hh] = mn;
            }

        // ---- p = exp(S - m), write rounded p to Ps, accumulate row sums ----
        float rs[4][2];
#pragma unroll
        for (int mt = 0; mt < 4; mt++) { rs[mt][0] = 0.f; rs[mt][1] = 0.f; }
#pragma unroll
        for (int mt = 0; mt < 4; mt++)
#pragma unroll
            for (int hh = 0; hh < 2; hh++) {
                const int row = wm * 64 + mt * 16 + hh * 8 + g;
#pragma unroll
                for (int nt = 0; nt < 4; nt++) {
#pragma unroll
                    for (int pp = 0; pp < 2; pp++) {
                        const int col = wn * 32 + nt * 8 + 2 * t + pp;
                        float p = __expf(Sa[mt][nt][hh * 2 + pp] - mnew[mt][hh]);
                        rs[mt][hh] += p;
                        Ps[(col >> 5) * CHUNKF + row * ASTR + (col & 31)] = tf32r(p);
                    }
                }
            }
#pragma unroll
        for (int mt = 0; mt < 4; mt++)
#pragma unroll
            for (int hh = 0; hh < 2; hh++) {
                rs[mt][hh] += __shfl_xor_sync(0xffffffffu, rs[mt][hh], 1);
                rs[mt][hh] += __shfl_xor_sync(0xffffffffu, rs[mt][hh], 2);
            }
        __syncthreads();   // done reading max-phase red
        if (t == 0) {
#pragma unroll
            for (int mt = 0; mt < 4; mt++)
#pragma unroll
                for (int hh = 0; hh < 2; hh++)
                    red[wn * 128 + wm * 64 + mt * 16 + hh * 8 + g] = rs[mt][hh];
        }
        __syncthreads();
#pragma unroll
        for (int mt = 0; mt < 4; mt++)
#pragma unroll
            for (int hh = 0; hh < 2; hh++) {
                const int r = wm * 64 + mt * 16 + hh * 8 + g;
                float tl = red[r] + red[128 + r] + red[256 + r] + red[384 + r];
                lrun[mt][hh] = lrun[mt][hh] * scal[mt][hh] + tl;
            }
        // rescale O accumulators
#pragma unroll
        for (int mt = 0; mt < 4; mt++)
#pragma unroll
            for (int nt = 0; nt < 4; nt++) {
                Oa[mt][nt][0] *= scal[mt][0];
                Oa[mt][nt][1] *= scal[mt][0];
                Oa[mt][nt][2] *= scal[mt][1];
                Oa[mt][nt][3] *= scal[mt][1];
            }
        __syncthreads();   // Ps fully written, red reads done

        // ---- O += P @ V (4 s-chunks over VT, double-buffered) ----
        load_kb(KB0, g_VT + (size_t)(h * DK) * SEQ + s0, SEQ);
        cp_commit();
        for (int kc = 0; kc < 4; kc++) {
            float* cur = (kc & 1) ? KB1 : KB0;
            float* nxt = (kc & 1) ? KB0 : KB1;
            cp_wait_all();
            __syncthreads();
            if (kc < 3) {
                load_kb(nxt, g_VT + (size_t)(h * DK) * SEQ + s0 + (kc + 1) * 32, SEQ);
                cp_commit();
            }
            mma_tile(Oa, Ps + kc * CHUNKF, cur);
            __syncthreads();
        }
    }

    // ---- final: O /= l, round, store ----
#pragma unroll
    for (int mt = 0; mt < 4; mt++)
#pragma unroll
        for (int hh = 0; hh < 2; hh++) {
            const float inv = 1.f / lrun[mt][hh];
            const int row = qrow0 + wm * 64 + mt * 16 + hh * 8 + g;
#pragma unroll
            for (int nt = 0; nt < 4; nt++) {
                const int col = h * DK + wn * 32 + nt * 8 + 2 * t;
                float v0 = tf32r(Oa[mt][nt][hh * 2 + 0] * inv);
                float v1 = tf32r(Oa[mt][nt][hh * 2 + 1] * inv);
                *(float2*)(g_O + (size_t)row * DM + col) = make_float2(v0, v1);
            }
        }
}

// ---------------- elementwise tf32 round (RN) ----------------
__global__ __launch_bounds__(256) void round_tf32_kernel(const float4* __restrict__ in,
                                                         float4* __restrict__ out, int n4)
{
    int i = blockIdx.x * 256 + threadIdx.x;
    if (i < n4) {
        float4 v = in[i];
        v.x = tf32r(v.x); v.y = tf32r(v.y); v.z = tf32r(v.z); v.w = tf32r(v.w);
        out[i] = v;
    }
}

// ---------------- exact fp32 mi path ----------------
__global__ __launch_bounds__(256) void xbar_kernel(const float* __restrict__ x)
{
    const int d = blockIdx.x * 256 + threadIdx.x;
    float s = 0.f;
    for (int i = 0; i < SEQ; i++) s += x[(size_t)i * DM + d];
    g_xbar[d] = s * (1.f / (float)SEQ);
}

__global__ __launch_bounds__(256) void mi_kernel(const float* __restrict__ fiber_w,
                                                 const float* __restrict__ fiber_b)
{
    const int f = blockIdx.x;
    const int t = threadIdx.x;
    const float* wr = fiber_w + (size_t)f * DM;
    float s = 0.f;
    for (int d = t; d < DM; d += 256) s += g_xbar[d] * wr[d];
    __shared__ float red[256];
    red[t] = s;
    __syncthreads();
    for (int off = 128; off > 0; off >>= 1) {
        if (t < off) red[t] += red[t + off];
        __syncthreads();
    }
    if (t == 0) g_mi[f] = red[0] + fiber_b[f];
}

__global__ __launch_bounds__(64) void fiber_mlp_kernel(
    const float* __restrict__ fm1_w, const float* __restrict__ fm1_b,
    const float* __restrict__ fm2_w, const float* __restrict__ fm2_b,
    const float* __restrict__ cmod, float* cimean_out)
{
    __shared__ float mi[FIB], h[FIB / 2], raw[FIB];
    const int t = threadIdx.x;
    mi[t] = g_mi[t];
    __syncthreads();
    if (t < 32) {
        float s = fm1_b[t];
        for (int f = 0; f < FIB; f++) s = fmaf(fm1_w[t * FIB + f], mi[f], s);
        h[t] = fmaxf(s, 0.f);
    }
    __syncthreads();
    float r = fm2_b[t];
    for (int j = 0; j < 32; j++) r = fmaf(fm2_w[t * 32 + j], h[j], r);
    raw[t] = r;
    __syncthreads();
    for (int gc = 0; gc < FIB; gc++)
        g_metric[t * FIB + gc] = raw[t] * raw[gc] + ((t == gc) ? 0.1f : 0.f);
    if (t == 0 && cimean_out) {
        float acc = 0.f;
        for (int f = 0; f < FIB; f++) {
            float s = 0.f;
            for (int gc = 0; gc < FIB; gc++) {
                float m = raw[f] * raw[gc] + ((f == gc) ? 0.1f : 0.f);
                s = fmaf(m, mi[gc], s);
            }
            acc = fmaf(mi[f], s, acc);
            acc = fmaf(mi[f], cmod[f * (FIB + 1)], acc);
        }
        *cimean_out = acc;
    }
}

// G = FP @ metric (tf32-rounded), curv' = 0.1 * FP . diag(cmod)
__global__ __launch_bounds__(256) void g_and_curv_kernel(const float* __restrict__ cmod)
{
    __shared__ float Ms[FIB * FIB];
    __shared__ float dg[FIB];
    const int t = threadIdx.x;
    for (int i = t; i < FIB * FIB; i += 256) Ms[i] = g_metric[i];
    if (t < FIB) dg[t] = cmod[t * (FIB + 1)];
    __syncthreads();

    const int idx  = blockIdx.x * 256 + t;
    const int i    = idx >> 6;
    const int gcol = idx & 63;
    const float* fr = g_FP + (size_t)i * FIB;
    float s = 0.f;
#pragma unroll 8
    for (int f = 0; f < FIB; f++) s = fmaf(fr[f], Ms[f * FIB + gcol], s);
    g_G[idx] = tf32r(s);
    if (gcol == 0) {
        float c = 0.f;
#pragma unroll 8
        for (int f = 0; f < FIB; f++) c = fmaf(fr[f], dg[f], c);
        g_curv[i] = 0.1f * c;
    }
}

// ---------------- launch --------------------------------------------------
extern "C" void kernel_launch(void* const* d_in, const int* in_sizes, int n_in,
                              void* d_out, int out_size)
{
    const float* x       = (const float*)d_in[0];
    const float* wq      = (const float*)d_in[2];
    const float* wk      = (const float*)d_in[3];
    const float* wv      = (const float*)d_in[4];
    const float* wo_w    = (const float*)d_in[5];
    const float* wo_b    = (const float*)d_in[6];
    const float* fiber_w = (const float*)d_in[7];
    const float* fiber_b = (const float*)d_in[8];
    const float* fm1_w   = (const float*)d_in[9];
    const float* fm1_b   = (const float*)d_in[10];
    const float* fm2_w   = (const float*)d_in[11];
    const float* fm2_b   = (const float*)d_in[12];
    const float* cmod    = (const float*)d_in[13];
    float* out = (float*)d_out;

    float *X, *WQ, *WK, *WV, *WO, *FW, *Q, *Kp, *VT, *O, *FP, *G, *MOD;
    cudaGetSymbolAddress((void**)&X,   g_X);
    cudaGetSymbolAddress((void**)&WQ,  g_WQ);
    cudaGetSymbolAddress((void**)&WK,  g_WK);
    cudaGetSymbolAddress((void**)&WV,  g_WV);
    cudaGetSymbolAddress((void**)&WO,  g_WO);
    cudaGetSymbolAddress((void**)&FW,  g_FW);
    cudaGetSymbolAddress((void**)&Q,   g_Q);
    cudaGetSymbolAddress((void**)&Kp,  g_K);
    cudaGetSymbolAddress((void**)&VT,  g_VT);
    cudaGetSymbolAddress((void**)&O,   g_O);
    cudaGetSymbolAddress((void**)&FP,  g_FP);
    cudaGetSymbolAddress((void**)&G,   g_G);
    cudaGetSymbolAddress((void**)&MOD, g_MOD);

    float* cimean_out = (out_size > SEQ * DM) ? (out + (size_t)SEQ * DM) : (float*)0;

    const int SMEM  = 4 * TILEF * 4;                     // 73728
    const int FSMEM = 10 * CHUNKF * 4 + 4 * 128 * 4;     // 186368
    cudaFuncSetAttribute(mma_gemm, cudaFuncAttributeMaxDynamicSharedMemorySize, SMEM);
    cudaFuncSetAttribute(flash_attn_kernel, cudaFuncAttributeMaxDynamicSharedMemorySize, FSMEM);

    const dim3 blk(256);

    // 0. exact fp32 mi path
    xbar_kernel<<<DM / 256, blk>>>(x);
    mi_kernel<<<FIB, blk>>>(fiber_w, fiber_b);
    fiber_mlp_kernel<<<1, FIB>>>(fm1_w, fm1_b, fm2_w, fm2_b, cmod, cimean_out);

    // 1. RN-round external MMA operands
    const int n4m = (SEQ * DM) / 4;
    round_tf32_kernel<<<(n4m + 255) / 256, blk>>>((const float4*)x,  (float4*)X,  n4m);
    round_tf32_kernel<<<(n4m + 255) / 256, blk>>>((const float4*)wq, (float4*)WQ, n4m);
    round_tf32_kernel<<<(n4m + 255) / 256, blk>>>((const float4*)wk, (float4*)WK, n4m);
    round_tf32_kernel<<<(n4m + 255) / 256, blk>>>((const float4*)wv, (float4*)WV, n4m);
    round_tf32_kernel<<<(n4m + 255) / 256, blk>>>((const float4*)wo_w, (float4*)WO, n4m);
    const int n4f = (FIB * DM) / 4;
    round_tf32_kernel<<<(n4f + 255) / 256, blk>>>((const float4*)fiber_w, (float4*)FW, n4f);

    const dim3 gProj(DM / 128, SEQ / 128, 1);
    const float rsdk = 1.f / sqrtf((float)DK);

    // 2. Q' = (X @ WQ^T) / sqrt(dk)  (rounded)
    mma_gemm<<<gProj, blk, SMEM>>>(X, WQ, Q, DM, DM, DM, DM, DM, 0, 0, 0,
                                   rsdk, 0, 0, 1);
    // 3. K = X @ WK^T (rounded)
    mma_gemm<<<gProj, blk, SMEM>>>(X, WK, Kp, DM, DM, DM, DM, DM, 0, 0, 0,
                                   1.f, 0, 0, 1);
    // 4. VT = (X @ WV^T)^T (rounded)
    mma_gemm<<<gProj, blk, SMEM>>>(X, WV, VT, DM, DM, DM, DM, SEQ, 0, 0, 0,
                                   1.f, 0, 1, 1);
    // 5. FP = X @ FW^T + fiber_b (rounded)
    mma_gemm<<<dim3(1, SEQ / 128, 1), blk, SMEM>>>(X, FW, FP, FIB, DM, DM, DM, FIB,
                                                   0, 0, 0, 1.f, fiber_b, 0, 1);
    // 6. G, curv'
    g_and_curv_kernel<<<(SEQ * FIB) / 256, 256>>>(cmod);

    // 7. MOD' = 0.1 * (G @ FP^T)
    mma_gemm<<<dim3(SEQ / 128, SEQ / 128, 1), blk, SMEM>>>(
        G, FP, MOD, SEQ, FIB, FIB, FIB, SEQ, 0, 0, 0, 0.1f, 0, 0, 0);

    // 8. fused attention
    flash_attn_kernel<<<dim3(SEQ / 128, NH), blk, FSMEM>>>();

    // 9. out = O @ WO^T + wo_b
    mma_gemm<<<gProj, blk, SMEM>>>(O, WO, out, DM, DM, DM, DM, DM, 0, 0, 0,
                                   1.f, wo_b, 0, 0);
}